// round 3
// baseline (speedup 1.0000x reference)
#include <cuda_runtime.h>

#define HH 8192
#define WW 512
#define NPIX (HH * WW)
#define TG22F 0.4142135623730951f
#define TS 32
#define IMGD 36
#define MAGD 34

// Static scratch (allocation-free rule)
__device__ unsigned char g_mask[NPIX];   // bit0 = weak, bit1 = strong
__device__ int           g_label[NPIX];
__device__ unsigned char g_flag[NPIX];

// K1: fused Sobel + channel argmax + NMS + thresholds + CCL init, smem-tiled.
__global__ __launch_bounds__(256) void k_gradnms(const float* __restrict__ x) {
    __shared__ float         simg[3][IMGD][IMGD];
    __shared__ float         smag[MAGD][MAGD];
    __shared__ unsigned char sdir[MAGD][MAGD];

    int tw = blockIdx.x & 15;          // 512/32 = 16 tiles across
    int tr = blockIdx.x >> 4;
    int r0 = tr * TS, w0 = tw * TS;
    int tid = threadIdx.x;

    // Stage image tile + 2-halo, with uint8 conversion (replicate border like cv2)
    for (int idx = tid; idx < 3 * IMGD * IMGD; idx += 256) {
        int c   = idx / (IMGD * IMGD);
        int rem = idx - c * IMGD * IMGD;
        int iy  = rem / IMGD, ix = rem - iy * IMGD;
        int gr = min(max(r0 - 2 + iy, 0), HH - 1);
        int gw = min(max(w0 - 2 + ix, 0), WW - 1);
        int b = gr >> 9, h = gr & 511;
        float v = __ldg(&x[(((size_t)(b * 3 + c) * 512 + h) * 512) + gw]);
        // exact XLA op order: floor(((x+1)*0.5)*255), clip — no FMA contraction
        float t = floorf(__fmul_rn(__fmul_rn(__fadd_rn(v, 1.0f), 0.5f), 255.0f));
        simg[c][iy][ix] = fminf(fmaxf(t, 0.0f), 255.0f);
    }
    __syncthreads();

    // Sobel + channel argmax over mag tile (+1 halo). Outside-strip mag = 0 (NMS zero-pad).
    for (int idx = tid; idx < MAGD * MAGD; idx += 256) {
        int my = idx / MAGD, mx = idx - my * MAGD;
        int gr = r0 - 1 + my, gw = w0 - 1 + mx;
        float bm = 0.0f; unsigned char d = 0;
        if ((unsigned)gr < (unsigned)HH && (unsigned)gw < (unsigned)WW) {
            bm = -1.0f; float bgx = 0.0f, bgy = 0.0f;
#pragma unroll
            for (int c = 0; c < 3; c++) {
                float a00 = simg[c][my][mx],     a01 = simg[c][my][mx + 1],     a02 = simg[c][my][mx + 2];
                float a10 = simg[c][my + 1][mx],                                a12 = simg[c][my + 1][mx + 2];
                float a20 = simg[c][my + 2][mx], a21 = simg[c][my + 2][mx + 1], a22 = simg[c][my + 2][mx + 2];
                float gx = (a02 + 2.0f * a12 + a22) - (a00 + 2.0f * a10 + a20);
                float gy = (a20 + 2.0f * a21 + a22) - (a00 + 2.0f * a01 + a02);
                float m = fabsf(gx) + fabsf(gy);
                if (m > bm) { bm = m; bgx = gx; bgy = gy; }  // strict > == first-max argmax
            }
            float ax = fabsf(bgx), ay = fabsf(bgy);
            if (ay < __fmul_rn(TG22F, ax))      d = 0;
            else if (__fmul_rn(ay, TG22F) > ax) d = 1;
            else d = (__fmul_rn(bgx, bgy) >= 0.0f) ? 2 : 3;
        }
        smag[my][mx] = bm;
        sdir[my][mx] = d;
    }
    __syncthreads();

    // NMS + thresholds for the interior 32x32; init labels/flags only at weak pixels.
    for (int q = tid; q < TS * TS; q += 256) {
        int ty = q >> 5, tx = q & 31;
        int my = ty + 1, mx = tx + 1;
        float m = smag[my][mx];
        int d = sdir[my][mx];
        float n1, n2;
        if (d == 0)      { n1 = smag[my][mx - 1];     n2 = smag[my][mx + 1]; }
        else if (d == 1) { n1 = smag[my - 1][mx];     n2 = smag[my + 1][mx]; }
        else if (d == 2) { n1 = smag[my - 1][mx - 1]; n2 = smag[my + 1][mx + 1]; }
        else             { n1 = smag[my - 1][mx + 1]; n2 = smag[my + 1][mx - 1]; }
        bool keep = (m > n1) && (m >= n2);
        unsigned char msk = 0;
        if (keep && (m > 100.0f)) msk = 1;
        if (keep && (m > 200.0f)) msk = 3;
        int i = (r0 + ty) * WW + (w0 + tx);
        g_mask[i] = msk;
        if (msk) { g_label[i] = i; g_flag[i] = 0; }  // only weak slots are ever read
    }
}

// Union-find find WITH path halving — only inside k_merge (ECL-CC; races benign).
__device__ __forceinline__ int uf_find(int x) {
    int p = g_label[x];
    while (p != x) {
        int gp = g_label[p];
        if (gp != p) g_label[x] = gp;
        x = p; p = gp;
    }
    return x;
}

// Read-only find: no writes. Labels are static after k_merge completes.
__device__ __forceinline__ int uf_find_ro(int x) {
    int p = g_label[x];
    while (p != x) { x = p; p = g_label[x]; }
    return x;
}

// K2: one-pass CCL merge over weak mask
__global__ __launch_bounds__(256) void k_merge() {
    int i = blockIdx.x * blockDim.x + threadIdx.x;
    if (i >= NPIX) return;
    if (!(g_mask[i] & 1)) return;
    int w = i & (WW - 1), r = i >> 9;
    const int dr[4] = {0, 1, 1, 1};
    const int dw[4] = {1, -1, 0, 1};
#pragma unroll
    for (int k = 0; k < 4; k++) {
        int rr = r + dr[k], ww = w + dw[k];
        if ((unsigned)rr >= (unsigned)HH || (unsigned)ww >= (unsigned)WW) continue;
        int j = rr * WW + ww;
        if (!(g_mask[j] & 1)) continue;
        int a = uf_find(i), b = uf_find(j);
        while (a != b) {
            int hi = a > b ? a : b;
            int lo = a > b ? b : a;
            int old = atomicCAS(&g_label[hi], hi, lo);
            if (old == hi) break;
            a = uf_find(old);
            b = uf_find(lo);
        }
    }
}

// K3: strong pixels flag their component root (read-only walk — labels static now)
__global__ __launch_bounds__(256) void k_sflag() {
    int i = blockIdx.x * blockDim.x + threadIdx.x;
    if (i >= NPIX) return;
    if (!(g_mask[i] & 2)) return;
    g_flag[uf_find_ro(i)] = 1;
}

// K4: final ±1 output, 4 pixels/thread, float4 stores to 3 NCHW channel planes
__global__ __launch_bounds__(256) void k_out(float* __restrict__ out) {
    int t = blockIdx.x * blockDim.x + threadIdx.x;   // NPIX/4 threads
    int i0 = t * 4;
    if (i0 >= NPIX) return;
    int r = i0 >> 9;
    int w = i0 & (WW - 1);

    const uchar4 m4 = *(const uchar4*)&g_mask[i0];
    float v[4];
    const unsigned char mk[4] = {m4.x, m4.y, m4.z, m4.w};
#pragma unroll
    for (int k = 0; k < 4; k++) {
        bool edge = false;
        if (mk[k] & 1) edge = (g_flag[uf_find_ro(i0 + k)] != 0);
        v[k] = edge ? 1.0f : -1.0f;
    }
    float4 val = make_float4(v[0], v[1], v[2], v[3]);

    int b = r >> 9, h = r & 511;
    size_t base = ((size_t)(b * 3) * 512 + h) * 512 + w;
    *(float4*)&out[base]                 = val;
    *(float4*)&out[base + 512 * 512]     = val;
    *(float4*)&out[base + 2 * 512 * 512] = val;
}

extern "C" void kernel_launch(void* const* d_in, const int* in_sizes, int n_in,
                              void* d_out, int out_size) {
    const float* x = (const float*)d_in[0];
    float* out = (float*)d_out;
    k_gradnms<<<(HH / TS) * (WW / TS), 256>>>(x);
    k_merge<<<NPIX / 256, 256>>>();
    k_sflag<<<NPIX / 256, 256>>>();
    k_out<<<NPIX / 4 / 256, 256>>>(out);
}

// round 4
// speedup vs baseline: 1.8484x; 1.8484x over previous
#include <cuda_runtime.h>

#define HH 8192
#define WW 512
#define NPIX (HH * WW)
#define HB 4096
#define WB 256
#define NBLK (HB * WB)
#define TG22F 0.4142135623730951f
#define TS 32
#define IMGD 36
#define MAGD 34

// Static scratch: 1MB bmask + 4MB labels + 1MB flags
__device__ unsigned char g_bmask[NBLK];  // bits0-3: weak(w00,w01,w10,w11); bit4: any strong
__device__ int           g_blabel[NBLK];
__device__ unsigned char g_bflag[NBLK];

// K1: fused Sobel + channel argmax + NMS + thresholds + 2x2-block mask/CCL init
__global__ __launch_bounds__(256) void k_gradnms(const float* __restrict__ x) {
    __shared__ float         simg[3][IMGD][IMGD];
    __shared__ float         smag[MAGD][MAGD];
    __shared__ unsigned char sdir[MAGD][MAGD];
    __shared__ unsigned char smsk[TS][TS];

    int tw = blockIdx.x & 15;          // 512/32 = 16 tiles across
    int tr = blockIdx.x >> 4;
    int r0 = tr * TS, w0 = tw * TS;
    int tid = threadIdx.x;

    // Stage image tile + 2-halo with uint8 conversion (replicate border like cv2)
    for (int idx = tid; idx < 3 * IMGD * IMGD; idx += 256) {
        int c   = idx / (IMGD * IMGD);
        int rem = idx - c * IMGD * IMGD;
        int iy  = rem / IMGD, ix = rem - iy * IMGD;
        int gr = min(max(r0 - 2 + iy, 0), HH - 1);
        int gw = min(max(w0 - 2 + ix, 0), WW - 1);
        int b = gr >> 9, h = gr & 511;
        float v = __ldg(&x[(((size_t)(b * 3 + c) * 512 + h) * 512) + gw]);
        // exact XLA op order: floor(((x+1)*0.5)*255), clip — no FMA contraction
        float t = floorf(__fmul_rn(__fmul_rn(__fadd_rn(v, 1.0f), 0.5f), 255.0f));
        simg[c][iy][ix] = fminf(fmaxf(t, 0.0f), 255.0f);
    }
    __syncthreads();

    // Sobel + channel argmax over mag tile (+1 halo). Outside strip: mag = 0 (NMS zero-pad).
    for (int idx = tid; idx < MAGD * MAGD; idx += 256) {
        int my = idx / MAGD, mx = idx - my * MAGD;
        int gr = r0 - 1 + my, gw = w0 - 1 + mx;
        float bm = 0.0f; unsigned char d = 0;
        if ((unsigned)gr < (unsigned)HH && (unsigned)gw < (unsigned)WW) {
            bm = -1.0f; float bgx = 0.0f, bgy = 0.0f;
#pragma unroll
            for (int c = 0; c < 3; c++) {
                float a00 = simg[c][my][mx],     a01 = simg[c][my][mx + 1],     a02 = simg[c][my][mx + 2];
                float a10 = simg[c][my + 1][mx],                                a12 = simg[c][my + 1][mx + 2];
                float a20 = simg[c][my + 2][mx], a21 = simg[c][my + 2][mx + 1], a22 = simg[c][my + 2][mx + 2];
                float gx = (a02 + 2.0f * a12 + a22) - (a00 + 2.0f * a10 + a20);
                float gy = (a20 + 2.0f * a21 + a22) - (a00 + 2.0f * a01 + a02);
                float m = fabsf(gx) + fabsf(gy);
                if (m > bm) { bm = m; bgx = gx; bgy = gy; }  // strict > == first-max argmax
            }
            float ax = fabsf(bgx), ay = fabsf(bgy);
            if (ay < __fmul_rn(TG22F, ax))      d = 0;
            else if (__fmul_rn(ay, TG22F) > ax) d = 1;
            else d = (__fmul_rn(bgx, bgy) >= 0.0f) ? 2 : 3;
        }
        smag[my][mx] = bm;
        sdir[my][mx] = d;
    }
    __syncthreads();

    // NMS + thresholds for the interior 32x32 -> per-pixel weak/strong bits in smem
    for (int q = tid; q < TS * TS; q += 256) {
        int ty = q >> 5, tx = q & 31;
        int my = ty + 1, mx = tx + 1;
        float m = smag[my][mx];
        int d = sdir[my][mx];
        float n1, n2;
        if (d == 0)      { n1 = smag[my][mx - 1];     n2 = smag[my][mx + 1]; }
        else if (d == 1) { n1 = smag[my - 1][mx];     n2 = smag[my + 1][mx]; }
        else if (d == 2) { n1 = smag[my - 1][mx - 1]; n2 = smag[my + 1][mx + 1]; }
        else             { n1 = smag[my - 1][mx + 1]; n2 = smag[my + 1][mx - 1]; }
        bool keep = (m > n1) && (m >= n2);
        unsigned char msk = 0;
        if (keep && (m > 100.0f)) msk = 1;
        if (keep && (m > 200.0f)) msk = 3;
        smsk[ty][tx] = msk;
    }
    __syncthreads();

    // Pack 2x2 pixel blocks: 16x16 = 256 blocks per tile, one per thread
    {
        int byt = tid >> 4, bxt = tid & 15;
        unsigned char p00 = smsk[byt * 2][bxt * 2];
        unsigned char p01 = smsk[byt * 2][bxt * 2 + 1];
        unsigned char p10 = smsk[byt * 2 + 1][bxt * 2];
        unsigned char p11 = smsk[byt * 2 + 1][bxt * 2 + 1];
        unsigned char bm = (p00 & 1) | ((p01 & 1) << 1) | ((p10 & 1) << 2) | ((p11 & 1) << 3);
        if ((p00 | p01 | p10 | p11) & 2) bm |= 0x10;     // any strong
        int gby = tr * 16 + byt, gbx = tw * 16 + bxt;
        int bi = gby * WB + gbx;
        g_bmask[bi] = bm;
        if (bm & 0xF) { g_blabel[bi] = bi; g_bflag[bi] = 0; }
    }
}

// UF find WITH path halving — only inside k_merge (ECL-CC; races benign for partition)
__device__ __forceinline__ int uf_find(int x) {
    int p = g_blabel[x];
    while (p != x) {
        int gp = g_blabel[p];
        if (gp != p) g_blabel[x] = gp;
        x = p; p = gp;
    }
    return x;
}

// Read-only find: labels static after k_merge
__device__ __forceinline__ int uf_find_ro(int x) {
    int p = g_blabel[x];
    while (p != x) { x = p; p = g_blabel[x]; }
    return x;
}

__device__ __forceinline__ void uf_union(int i, int j) {
    int a = uf_find(i), b = uf_find(j);
    while (a != b) {
        int hi = a > b ? a : b;
        int lo = a > b ? b : a;
        int old = atomicCAS(&g_blabel[hi], hi, lo);
        if (old == hi) break;
        a = uf_find(old);
        b = uf_find(lo);
    }
}

// K2: block-level CCL merge (forward directions E, SW, S, SE cover all pixel adjacencies)
__global__ __launch_bounds__(256) void k_merge() {
    int bi = blockIdx.x * blockDim.x + threadIdx.x;
    if (bi >= NBLK) return;
    unsigned char m = g_bmask[bi];
    if (!(m & 0xF)) return;
    int bx = bi & (WB - 1), by = bi >> 8;

    if (bx + 1 < WB) {                       // E: right col of A vs left col of B
        unsigned char me = g_bmask[bi + 1];
        if ((m & 0xA) && (me & 0x5)) uf_union(bi, bi + 1);
    }
    if (by + 1 < HB) {
        unsigned char ms = g_bmask[bi + WB]; // S: bottom row vs top row
        if ((m & 0xC) && (ms & 0x3)) uf_union(bi, bi + WB);
        if (bx + 1 < WB) {                   // SE: a11 vs se00
            unsigned char mse = g_bmask[bi + WB + 1];
            if ((m & 0x8) && (mse & 0x1)) uf_union(bi, bi + WB + 1);
        }
        if (bx > 0) {                        // SW: a10 vs sw01
            unsigned char msw = g_bmask[bi + WB - 1];
            if ((m & 0x4) && (msw & 0x2)) uf_union(bi, bi + WB - 1);
        }
    }
}

// K3: blocks containing a strong pixel flag their component root (read-only walk)
__global__ __launch_bounds__(256) void k_sflag() {
    int bi = blockIdx.x * blockDim.x + threadIdx.x;
    if (bi >= NBLK) return;
    if (!(g_bmask[bi] & 0x10)) return;
    g_bflag[uf_find_ro(bi)] = 1;
}

// K4: ±1 output, 4 pixels/thread (spanning 2 blocks), float4 stores to 3 NCHW planes
__global__ __launch_bounds__(256) void k_out(float* __restrict__ out) {
    int t = blockIdx.x * blockDim.x + threadIdx.x;   // NPIX/4 threads
    int i0 = t * 4;
    if (i0 >= NPIX) return;
    int r = i0 >> 9;
    int w0 = i0 & (WW - 1);
    int by = r >> 1, bx0 = w0 >> 1, hp = r & 1;
    int bi0 = by * WB + bx0;

    unsigned char m0 = g_bmask[bi0], m1 = g_bmask[bi0 + 1];
    int sh = hp * 2;
    bool k0 = (m0 >> sh) & 1, k1 = (m0 >> (sh + 1)) & 1;
    bool k2 = (m1 >> sh) & 1, k3 = (m1 >> (sh + 1)) & 1;

    bool f0 = false, f1 = false;
    if (k0 | k1) f0 = (g_bflag[uf_find_ro(bi0)] != 0);
    if (k2 | k3) f1 = (g_bflag[uf_find_ro(bi0 + 1)] != 0);

    float4 val = make_float4((k0 && f0) ? 1.0f : -1.0f,
                             (k1 && f0) ? 1.0f : -1.0f,
                             (k2 && f1) ? 1.0f : -1.0f,
                             (k3 && f1) ? 1.0f : -1.0f);

    int b = r >> 9, h = r & 511;
    size_t base = ((size_t)(b * 3) * 512 + h) * 512 + w0;
    *(float4*)&out[base]                 = val;
    *(float4*)&out[base + 512 * 512]     = val;
    *(float4*)&out[base + 2 * 512 * 512] = val;
}

extern "C" void kernel_launch(void* const* d_in, const int* in_sizes, int n_in,
                              void* d_out, int out_size) {
    const float* x = (const float*)d_in[0];
    float* out = (float*)d_out;
    k_gradnms<<<(HH / TS) * (WW / TS), 256>>>(x);
    k_merge<<<NBLK / 256, 256>>>();
    k_sflag<<<NBLK / 256, 256>>>();
    k_out<<<NPIX / 4 / 256, 256>>>(out);
}

// round 5
// speedup vs baseline: 2.0167x; 1.0910x over previous
#include <cuda_runtime.h>

#define HH 8192
#define WW 512
#define NPIX (HH * WW)
#define HB 4096
#define WB 256
#define NBLK (HB * WB)
#define TG22F 0.4142135623730951f

#define TSW 64
#define TSH 32
#define IMW 68    // staged cols: w0-2 .. w0+65
#define IMW_S 72  // smem stride (bytes)
#define IMH 36
#define MGW 66    // mag cols: w0-1 .. w0+64
#define MGW_S 68
#define MGH 34

// Static scratch: 1MB bmask + 4MB labels + 1MB flags
__device__ unsigned char g_bmask[NBLK];  // bits0-3: weak(w00,w01,w10,w11); bit4: any strong
__device__ int           g_blabel[NBLK];
__device__ unsigned char g_bflag[NBLK];

__device__ __forceinline__ int bytev(unsigned v, int k) { return (int)((v >> (8 * k)) & 0xFF); }

// K1: fused uint8-convert + int Sobel + channel argmax + NMS + 2x2-block mask/CCL init
__global__ __launch_bounds__(256) void k_gradnms(const float* __restrict__ x) {
    __shared__ unsigned char simg[3][IMH][IMW_S];
    __shared__ short         smag[MGH][MGW_S];
    __shared__ unsigned char sdir[MGH][MGW_S];
    __shared__ unsigned char smsk[TSH][TSW];

    int tw = blockIdx.x & 7;           // 512/64 = 8 tiles across
    int tr = blockIdx.x >> 3;
    int r0 = tr * TSH, w0 = tw * TSW;
    int tid = threadIdx.x;

    // Stage image tile + 2-halo, converting to uint8 (replicate border like cv2).
    // t = floor(((v+1)*0.5)*255) clipped to [0,255] — exact XLA op order, no FMA.
    for (int idx = tid; idx < 3 * IMH * IMW; idx += 256) {
        int c   = idx / (IMH * IMW);
        int rem = idx - c * IMH * IMW;
        int iy  = rem / IMW, ix = rem - iy * IMW;
        int gr = min(max(r0 - 2 + iy, 0), HH - 1);
        int gw = min(max(w0 - 2 + ix, 0), WW - 1);
        int b = gr >> 9, h = gr & 511;
        float v = __ldg(&x[(((size_t)(b * 3 + c) * 512 + h) * 512) + gw]);
        float t = floorf(__fmul_rn(__fmul_rn(__fadd_rn(v, 1.0f), 0.5f), 255.0f));
        simg[c][iy][ix] = (unsigned char)(int)fminf(fmaxf(t, 0.0f), 255.0f);
    }
    __syncthreads();

    // Int Sobel + channel argmax, 4 mag pixels per iteration (quad).
    // mag pixel mx uses simg cols mx..mx+2 (simg col j = global w0-2+j).
    for (int q = tid; q < MGH * 17; q += 256) {
        int my = q / 17, qx = q - my * 17;
        int mx0 = qx * 4;
        int bm[4]  = {-1, -1, -1, -1};
        int bgx[4] = {0, 0, 0, 0}, bgy[4] = {0, 0, 0, 0};
#pragma unroll
        for (int c = 0; c < 3; c++) {
            const unsigned char* bp = &simg[c][my][mx0];
            unsigned t0 = *(const unsigned*)(bp);
            unsigned t1 = *(const unsigned*)(bp + 4);
            unsigned m0 = *(const unsigned*)(bp + IMW_S);
            unsigned m1 = *(const unsigned*)(bp + IMW_S + 4);
            unsigned b0 = *(const unsigned*)(bp + 2 * IMW_S);
            unsigned b1 = *(const unsigned*)(bp + 2 * IMW_S + 4);
            int cg[6], dr[6];
#pragma unroll
            for (int j = 0; j < 4; j++) {
                int tv = bytev(t0, j), mv = bytev(m0, j), bv = bytev(b0, j);
                cg[j] = tv + 2 * mv + bv;
                dr[j] = bv - tv;
            }
#pragma unroll
            for (int j = 0; j < 2; j++) {
                int tv = bytev(t1, j), mv = bytev(m1, j), bv = bytev(b1, j);
                cg[4 + j] = tv + 2 * mv + bv;
                dr[4 + j] = bv - tv;
            }
#pragma unroll
            for (int p = 0; p < 4; p++) {
                int gx = cg[p + 2] - cg[p];
                int gy = dr[p] + 2 * dr[p + 1] + dr[p + 2];
                int mm = abs(gx) + abs(gy);
                if (mm > bm[p]) { bm[p] = mm; bgx[p] = gx; bgy[p] = gy; }  // first-max argmax
            }
        }
#pragma unroll
        for (int p = 0; p < 4; p++) {
            int mx = mx0 + p;
            if (mx >= MGW_S) continue;
            int gr = r0 - 1 + my, gw = w0 - 1 + mx;
            short mv = 0; unsigned char d = 0;
            if (mx < MGW && (unsigned)gr < (unsigned)HH && (unsigned)gw < (unsigned)WW) {
                mv = (short)bm[p];
                float fgx = __int2float_rn(bgx[p]), fgy = __int2float_rn(bgy[p]);
                float ax = fabsf(fgx), ay = fabsf(fgy);
                if (ay < __fmul_rn(TG22F, ax))      d = 0;
                else if (__fmul_rn(ay, TG22F) > ax) d = 1;
                else d = (__fmul_rn(fgx, fgy) >= 0.0f) ? 2 : 3;
            }
            smag[my][mx] = mv;
            sdir[my][mx] = d;
        }
    }
    __syncthreads();

    // NMS + thresholds (all-int, exact) for interior 32x64 -> per-pixel bits
    for (int q = tid; q < TSH * TSW; q += 256) {
        int ty = q >> 6, tx = q & 63;
        int my = ty + 1, mx = tx + 1;
        int m = smag[my][mx];
        int d = sdir[my][mx];
        int n1, n2;
        if (d == 0)      { n1 = smag[my][mx - 1];     n2 = smag[my][mx + 1]; }
        else if (d == 1) { n1 = smag[my - 1][mx];     n2 = smag[my + 1][mx]; }
        else if (d == 2) { n1 = smag[my - 1][mx - 1]; n2 = smag[my + 1][mx + 1]; }
        else             { n1 = smag[my - 1][mx + 1]; n2 = smag[my + 1][mx - 1]; }
        bool keep = (m > n1) && (m >= n2);
        unsigned char msk = 0;
        if (keep && (m > 100)) msk = 1;
        if (keep && (m > 200)) msk = 3;
        smsk[ty][tx] = msk;
    }
    __syncthreads();

    // Pack 2x2 pixel blocks: 16x32 = 512 blocks per tile
    for (int q = tid; q < 512; q += 256) {
        int byt = q >> 5, bxt = q & 31;
        unsigned char p00 = smsk[byt * 2][bxt * 2];
        unsigned char p01 = smsk[byt * 2][bxt * 2 + 1];
        unsigned char p10 = smsk[byt * 2 + 1][bxt * 2];
        unsigned char p11 = smsk[byt * 2 + 1][bxt * 2 + 1];
        unsigned char bmv = (p00 & 1) | ((p01 & 1) << 1) | ((p10 & 1) << 2) | ((p11 & 1) << 3);
        if ((p00 | p01 | p10 | p11) & 2) bmv |= 0x10;
        int gby = tr * 16 + byt, gbx = tw * 32 + bxt;
        int bi = gby * WB + gbx;
        g_bmask[bi] = bmv;
        if (bmv & 0xF) { g_blabel[bi] = bi; g_bflag[bi] = 0; }
    }
}

// UF find WITH path halving — only inside k_merge (ECL-CC; races benign for partition)
__device__ __forceinline__ int uf_find(int x) {
    int p = g_blabel[x];
    while (p != x) {
        int gp = g_blabel[p];
        if (gp != p) g_blabel[x] = gp;
        x = p; p = gp;
    }
    return x;
}

// Read-only find: labels static after k_merge
__device__ __forceinline__ int uf_find_ro(int x) {
    int p = g_blabel[x];
    while (p != x) { x = p; p = g_blabel[x]; }
    return x;
}

__device__ __forceinline__ void uf_union(int i, int j) {
    int a = uf_find(i), b = uf_find(j);
    while (a != b) {
        int hi = a > b ? a : b;
        int lo = a > b ? b : a;
        int old = atomicCAS(&g_blabel[hi], hi, lo);
        if (old == hi) break;
        a = uf_find(old);
        b = uf_find(lo);
    }
}

// K2: block-level CCL merge (E, S, SE, SW cover all pixel adjacencies)
__global__ __launch_bounds__(256) void k_merge() {
    int bi = blockIdx.x * blockDim.x + threadIdx.x;
    if (bi >= NBLK) return;
    unsigned char m = g_bmask[bi];
    if (!(m & 0xF)) return;
    int bx = bi & (WB - 1), by = bi >> 8;

    if (bx + 1 < WB) {
        unsigned char me = g_bmask[bi + 1];
        if ((m & 0xA) && (me & 0x5)) uf_union(bi, bi + 1);
    }
    if (by + 1 < HB) {
        unsigned char ms = g_bmask[bi + WB];
        if ((m & 0xC) && (ms & 0x3)) uf_union(bi, bi + WB);
        if (bx + 1 < WB) {
            unsigned char mse = g_bmask[bi + WB + 1];
            if ((m & 0x8) && (mse & 0x1)) uf_union(bi, bi + WB + 1);
        }
        if (bx > 0) {
            unsigned char msw = g_bmask[bi + WB - 1];
            if ((m & 0x4) && (msw & 0x2)) uf_union(bi, bi + WB - 1);
        }
    }
}

// K3: blocks containing a strong pixel flag their component root (read-only walk)
__global__ __launch_bounds__(256) void k_sflag() {
    int bi = blockIdx.x * blockDim.x + threadIdx.x;
    if (bi >= NBLK) return;
    if (!(g_bmask[bi] & 0x10)) return;
    g_bflag[uf_find_ro(bi)] = 1;
}

// K4: ±1 output, 8 pixels/thread (2x4 patch = both rows of 2 blocks), 6x float4 stores
__global__ __launch_bounds__(256) void k_out(float* __restrict__ out) {
    int t = blockIdx.x * blockDim.x + threadIdx.x;   // NPIX/8 threads
    if (t >= NPIX / 8) return;
    int pw = t & 127, py = t >> 7;
    int bi0 = py * WB + pw * 2;

    unsigned char m0 = g_bmask[bi0], m1 = g_bmask[bi0 + 1];
    bool f0 = false, f1 = false;
    if (m0 & 0xF) f0 = (g_bflag[uf_find_ro(bi0)] != 0);
    if (m1 & 0xF) f1 = (g_bflag[uf_find_ro(bi0 + 1)] != 0);

    float4 v0 = make_float4(((m0 & 1) && f0) ? 1.0f : -1.0f,
                            ((m0 & 2) && f0) ? 1.0f : -1.0f,
                            ((m1 & 1) && f1) ? 1.0f : -1.0f,
                            ((m1 & 2) && f1) ? 1.0f : -1.0f);
    float4 v1 = make_float4(((m0 & 4) && f0) ? 1.0f : -1.0f,
                            ((m0 & 8) && f0) ? 1.0f : -1.0f,
                            ((m1 & 4) && f1) ? 1.0f : -1.0f,
                            ((m1 & 8) && f1) ? 1.0f : -1.0f);

    int r = py * 2;                       // top row of the patch (same image as r+1)
    int b = r >> 9, h = r & 511;
    size_t base = ((size_t)(b * 3) * 512 + h) * 512 + pw * 4;
    *(float4*)&out[base]                       = v0;
    *(float4*)&out[base + 512]                 = v1;
    *(float4*)&out[base + 512 * 512]           = v0;
    *(float4*)&out[base + 512 * 512 + 512]     = v1;
    *(float4*)&out[base + 2 * 512 * 512]       = v0;
    *(float4*)&out[base + 2 * 512 * 512 + 512] = v1;
}

extern "C" void kernel_launch(void* const* d_in, const int* in_sizes, int n_in,
                              void* d_out, int out_size) {
    const float* x = (const float*)d_in[0];
    float* out = (float*)d_out;
    k_gradnms<<<(HH / TSH) * (WW / TSW), 256>>>(x);
    k_merge<<<NBLK / 256, 256>>>();
    k_sflag<<<NBLK / 256, 256>>>();
    k_out<<<NPIX / 8 / 256, 256>>>(out);
}